// round 13
// baseline (speedup 1.0000x reference)
#include <cuda_runtime.h>
#include <cuda_fp16.h>
#include <cstdint>

#define NN   50000
#define EE   400000
#define DIN  128
#define DH   512
#define NCLS 128
#define NBLK 196   // (NN + 255) / 256

// ---------------- scratch (allocation-free: device globals) ----------------
__device__ __half g_pre16[(size_t)NN * DH];
__device__ __half g_x16 [(size_t)NN * DIN];
__device__ __half g_agg16[(size_t)NN * DH];
__device__ __half g_h16 [(size_t)NN * DH];
__device__ __half g_w16 [720896];     // Wrel1|Wroot1|Wrel2|Wroot2|Wcls
__device__ float  g_stats[(size_t)NN * 2];   // per-row mean, rstd for LN2
__device__ int    g_deg[NN];
__device__ int    g_part[256];
__device__ int    g_rowptr[NN + 1];
__device__ int    g_cursor[NN];
__device__ int    g_csrc[EE];
__device__ float  g_cew [EE];

#define SWZ(x) ((x) ^ (((x) >> 3) & 0x70))

// ---------------- fused fp32->fp16 conversions + zero_deg ----------------
__global__ void f2h_zero_kernel(const float* __restrict__ x,
                                const float* __restrict__ Wrel1,
                                const float* __restrict__ Wroot1,
                                const float* __restrict__ Wrel2,
                                const float* __restrict__ Wroot2,
                                const float* __restrict__ Wcls,
                                __half* __restrict__ x16,
                                __half* __restrict__ w16)
{
    int gid = blockIdx.x * blockDim.x + threadIdx.x;
    if (gid >= 1780224) {
        int z = gid - 1780224;
        if (z < NN) g_deg[z] = 0;
        return;
    }
    const float* src;
    __half* dst;
    int i = gid;
    if (i < 1600000)        { src = x;      dst = x16;          }
    else if (i < 1616384)   { src = Wrel1;  dst = w16;          i -= 1600000; }
    else if (i < 1632768)   { src = Wroot1; dst = w16 + 65536;  i -= 1616384; }
    else if (i < 1698304)   { src = Wrel2;  dst = w16 + 131072; i -= 1632768; }
    else if (i < 1763840)   { src = Wroot2; dst = w16 + 393216; i -= 1698304; }
    else                    { src = Wcls;   dst = w16 + 655360; i -= 1763840; }
    float4 v = ((const float4*)src)[i];
    __half2 h0 = __floats2half2_rn(v.x, v.y);
    __half2 h1 = __floats2half2_rn(v.z, v.w);
    uint2 u;
    u.x = *(uint32_t*)&h0;
    u.y = *(uint32_t*)&h1;
    ((uint2*)dst)[i] = u;
}

// ---------------- CSR build ----------------
__global__ void hist_kernel(const int* __restrict__ dst) {
    int e = blockIdx.x * blockDim.x + threadIdx.x;
    if (e < EE) atomicAdd(&g_deg[dst[e]], 1);
}

__global__ void deg_partial_kernel() {
    int i = blockIdx.x * 256 + threadIdx.x;
    int v = (i < NN) ? g_deg[i] : 0;
    int lane = threadIdx.x & 31, w = threadIdx.x >> 5;
    #pragma unroll
    for (int off = 16; off; off >>= 1)
        v += __shfl_down_sync(0xffffffffu, v, off);
    __shared__ int ws[8];
    if (lane == 0) ws[w] = v;
    __syncthreads();
    if (threadIdx.x == 0) {
        int t = 0;
        #pragma unroll
        for (int q = 0; q < 8; q++) t += ws[q];
        g_part[blockIdx.x] = t;
    }
}

__global__ void scan_apply_kernel() {
    __shared__ int part[256];
    __shared__ int wsum[8];
    int t = threadIdx.x;
    part[t] = (t < NBLK) ? g_part[t] : 0;
    __syncthreads();
    #pragma unroll
    for (int off = 1; off < 256; off <<= 1) {
        int tv = (t >= off) ? part[t - off] : 0;
        __syncthreads();
        part[t] += tv;
        __syncthreads();
    }
    int blockoff = (blockIdx.x > 0) ? part[blockIdx.x - 1] : 0;

    int i = blockIdx.x * 256 + t;
    int d = (i < NN) ? g_deg[i] : 0;
    int lane = t & 31, w = t >> 5;
    int v = d;
    #pragma unroll
    for (int off = 1; off < 32; off <<= 1) {
        int u = __shfl_up_sync(0xffffffffu, v, off);
        if (lane >= off) v += u;
    }
    if (lane == 31) wsum[w] = v;
    __syncthreads();
    if (w == 0) {
        int x = (lane < 8) ? wsum[lane] : 0;
        #pragma unroll
        for (int off = 1; off < 8; off <<= 1) {
            int u = __shfl_up_sync(0xffffffffu, x, off);
            if (lane >= off) x += u;
        }
        if (lane < 8) wsum[lane] = x;
    }
    __syncthreads();
    int excl = (v - d) + (w > 0 ? wsum[w - 1] : 0) + blockoff;
    if (i < NN) {
        g_cursor[i]     = excl;
        g_rowptr[i + 1] = excl + d;
    }
    if (i == 0) g_rowptr[0] = 0;
}

__global__ void scatter_kernel(const int* __restrict__ src, const int* __restrict__ dst) {
    int e = blockIdx.x * blockDim.x + threadIdx.x;
    if (e >= EE) return;
    int s = src[e], d = dst[e];
    int p = atomicAdd(&g_cursor[d], 1);
    g_csrc[p] = s;
    g_cew[p] = 1.0f / (float)(s - d);   // pos = arange: exact in fp32
}

// ---------------- segment-max via gather (R12) ----------
template <int D>
__global__ void gather_max_kernel(const __half* __restrict__ X, __half* __restrict__ out) {
    const int TPN = D / 16;
    int gid  = blockIdx.x * blockDim.x + threadIdx.x;
    int node = gid / TPN;
    int lane = gid % TPN;
    if (node >= NN) return;
    int s = g_rowptr[node];
    int e = g_rowptr[node + 1];
    const float NEG = -3.402823466e+38f;
    float acc[16];
    #pragma unroll
    for (int q = 0; q < 16; q++) acc[q] = NEG;

    int   sn0 = 0, sn1 = 0;
    float ew0 = 0.f, ew1 = 0.f;
    if (s + 1 < e) {
        sn0 = g_csrc[s];     sn1 = g_csrc[s + 1];
        ew0 = g_cew[s];      ew1 = g_cew[s + 1];
    }

    int j = s;
    for (; j + 1 < e; j += 2) {
        float cw0 = ew0, cw1 = ew1;
        const uint4* r0 = (const uint4*)(X + (size_t)sn0 * D) + lane * 2;
        const uint4* r1 = (const uint4*)(X + (size_t)sn1 * D) + lane * 2;
        uint4 u0a = __ldg(r0);
        uint4 u0b = __ldg(r0 + 1);
        uint4 u1a = __ldg(r1);
        uint4 u1b = __ldg(r1 + 1);
        int nj = j + 2;
        if (nj + 1 < e) {
            sn0 = g_csrc[nj];     sn1 = g_csrc[nj + 1];
            ew0 = g_cew[nj];      ew1 = g_cew[nj + 1];
        }
        const uint32_t* p0a = &u0a.x;
        const uint32_t* p0b = &u0b.x;
        const uint32_t* p1a = &u1a.x;
        const uint32_t* p1b = &u1b.x;
        #pragma unroll
        for (int q = 0; q < 4; q++) {
            float2 f0 = __half22float2(*(const __half2*)&p0a[q]);
            float2 f1 = __half22float2(*(const __half2*)&p1a[q]);
            acc[q * 2 + 0] = fmaxf(acc[q * 2 + 0], fmaxf(f0.x * cw0, f1.x * cw1));
            acc[q * 2 + 1] = fmaxf(acc[q * 2 + 1], fmaxf(f0.y * cw0, f1.y * cw1));
            float2 g0 = __half22float2(*(const __half2*)&p0b[q]);
            float2 g1 = __half22float2(*(const __half2*)&p1b[q]);
            acc[8 + q * 2 + 0] = fmaxf(acc[8 + q * 2 + 0], fmaxf(g0.x * cw0, g1.x * cw1));
            acc[8 + q * 2 + 1] = fmaxf(acc[8 + q * 2 + 1], fmaxf(g0.y * cw0, g1.y * cw1));
        }
    }
    if (j < e) {
        int   sn = g_csrc[j];
        float ew = g_cew[j];
        const uint4* r = (const uint4*)(X + (size_t)sn * D) + lane * 2;
        uint4 ua = __ldg(r);
        uint4 ub = __ldg(r + 1);
        const uint32_t* pa = &ua.x;
        const uint32_t* pb = &ub.x;
        #pragma unroll
        for (int q = 0; q < 4; q++) {
            float2 f = __half22float2(*(const __half2*)&pa[q]);
            acc[q * 2 + 0] = fmaxf(acc[q * 2 + 0], f.x * ew);
            acc[q * 2 + 1] = fmaxf(acc[q * 2 + 1], f.y * ew);
            float2 g = __half22float2(*(const __half2*)&pb[q]);
            acc[8 + q * 2 + 0] = fmaxf(acc[8 + q * 2 + 0], g.x * ew);
            acc[8 + q * 2 + 1] = fmaxf(acc[8 + q * 2 + 1], g.y * ew);
        }
    }
    if (e == s) {
        #pragma unroll
        for (int q = 0; q < 16; q++) acc[q] = 0.f;
    }
    uint4 oa, ob;
    uint32_t* pa = &oa.x;
    uint32_t* pb = &ob.x;
    #pragma unroll
    for (int q = 0; q < 4; q++) {
        __half2 h0 = __floats2half2_rn(acc[q * 2],     acc[q * 2 + 1]);
        __half2 h1 = __floats2half2_rn(acc[8 + q * 2], acc[8 + q * 2 + 1]);
        pa[q] = *(uint32_t*)&h0;
        pb[q] = *(uint32_t*)&h1;
    }
    uint4* op = (uint4*)(out + (size_t)node * D) + lane * 2;
    op[0] = oa;
    op[1] = ob;
}

// ---------------- MMA helpers ----------------
__device__ __forceinline__ void mma16816(float* d, const uint32_t* a, const uint32_t* b) {
    asm volatile(
        "mma.sync.aligned.m16n8k16.row.col.f32.f16.f16.f32 "
        "{%0,%1,%2,%3}, {%4,%5,%6,%7}, {%8,%9}, {%0,%1,%2,%3};"
        : "+f"(d[0]), "+f"(d[1]), "+f"(d[2]), "+f"(d[3])
        : "r"(a[0]), "r"(a[1]), "r"(a[2]), "r"(a[3]), "r"(b[0]), "r"(b[1]));
}
__device__ __forceinline__ void ldsm_x4u(uint32_t* r, uint32_t a) {
    asm volatile("ldmatrix.sync.aligned.m8n8.x4.shared.b16 {%0,%1,%2,%3}, [%4];"
                 : "=r"(r[0]), "=r"(r[1]), "=r"(r[2]), "=r"(r[3]) : "r"(a));
}
__device__ __forceinline__ void ldsm_x2u(uint32_t* r, uint32_t a) {
    asm volatile("ldmatrix.sync.aligned.m8n8.x2.shared.b16 {%0,%1}, [%2];"
                 : "=r"(r[0]), "=r"(r[1]) : "r"(a));
}
__device__ __forceinline__ void cp16(uint32_t dst, const void* src, bool v) {
    int sz = v ? 16 : 0;
    asm volatile("cp.async.cg.shared.global [%0], [%1], 16, %2;"
                 :: "r"(dst), "l"(src), "r"(sz));
}

// ---------------- fp16 mma.sync dual-GEMM: 128x128, 256 thr, 2 CTA/SM ------
template <typename OutT>
__global__ void __launch_bounds__(256, 2)
mma_dual(const __half* __restrict__ A1, const __half* __restrict__ W1, int K1,
         const __half* __restrict__ A2, const __half* __restrict__ W2, int K2,
         const float* __restrict__ bias, OutT* __restrict__ C, int M, int N)
{
    extern __shared__ __align__(1024) char smem[];
    const uint32_t sbase = (uint32_t)__cvta_generic_to_shared(smem);
    const uint32_t ABYTES = 16384;
    const uint32_t BBYTES = 16384;

    const int tid = threadIdx.x;
    const int wid = tid >> 5, lid = tid & 31;
    const int wm = wid & 1, wn = wid >> 1;
    const int row0 = blockIdx.y * 128;
    const int col0 = blockIdx.x * 128;

    const int nc1 = K1 / 64;
    const int nc2 = A2 ? (K2 / 64) : 0;
    const int nch = nc1 + nc2;

    float acc[4][4][4];
    #pragma unroll
    for (int i = 0; i < 4; i++)
        #pragma unroll
        for (int j = 0; j < 4; j++)
            #pragma unroll
            for (int q = 0; q < 4; q++) acc[i][j][q] = 0.f;

    auto load_chunk = [&](int c, int buf) {
        const int pass = (c >= nc1);
        const __half* A = pass ? A2 : A1;
        const __half* W = pass ? W2 : W1;
        const int K  = pass ? K2 : K1;
        const int k0 = (pass ? (c - nc1) : c) * 64;
        const uint32_t sa  = sbase + (uint32_t)buf * ABYTES;
        const uint32_t sbb = sbase + 2 * ABYTES + (uint32_t)buf * BBYTES;
        int G = tid;
        #pragma unroll
        for (int rep = 0; rep < 4; rep++, G += 256) {
            int row = G >> 3, g = G & 7;
            bool v = (row0 + row) < M;
            size_t r = v ? (size_t)(row0 + row) : 0;
            cp16(sa + SWZ((uint32_t)row * 128 + g * 16), A + r * K + k0 + g * 8, v);
        }
        G = tid;
        #pragma unroll
        for (int rep = 0; rep < 4; rep++, G += 256) {
            int row = G >> 3, g = G & 7;
            cp16(sbb + SWZ((uint32_t)row * 128 + g * 16),
                 W + (size_t)(col0 + row) * K + k0 + g * 8, true);
        }
        asm volatile("cp.async.commit_group;" ::: "memory");
    };

    load_chunk(0, 0);
    for (int c = 0; c < nch; c++) {
        const int buf = c & 1;
        if (c + 1 < nch) {
            load_chunk(c + 1, (c + 1) & 1);
            asm volatile("cp.async.wait_group 1;" ::: "memory");
        } else {
            asm volatile("cp.async.wait_group 0;" ::: "memory");
        }
        __syncthreads();

        const uint32_t ca = sbase + (uint32_t)buf * ABYTES;
        const uint32_t cb = sbase + 2 * ABYTES + (uint32_t)buf * BBYTES;
        #pragma unroll
        for (int kb = 0; kb < 4; kb++) {
            uint32_t a[4][4], b[4][2];
            #pragma unroll
            for (int mi = 0; mi < 4; mi++) {
                uint32_t r = (uint32_t)(wm * 64 + mi * 16 + (lid & 15));
                ldsm_x4u(a[mi], ca + SWZ(r * 128 + kb * 32 + (lid >> 4) * 16));
            }
            #pragma unroll
            for (int ni = 0; ni < 4; ni++) {
                uint32_t n = (uint32_t)(wn * 32 + ni * 8 + (lid & 7));
                ldsm_x2u(b[ni], cb + SWZ(n * 128 + kb * 32 + ((lid >> 3) & 1) * 16));
            }
            #pragma unroll
            for (int mi = 0; mi < 4; mi++)
                #pragma unroll
                for (int ni = 0; ni < 4; ni++)
                    mma16816(acc[mi][ni], a[mi], b[ni]);
        }
        __syncthreads();
    }

    {
        const int lr = lid >> 2;
        const int lc = (lid & 3) * 2;
        #pragma unroll
        for (int ni = 0; ni < 4; ni++) {
            int col = col0 + wn * 32 + ni * 8 + lc;
            float b0 = bias[col], b1 = bias[col + 1];
            #pragma unroll
            for (int mi = 0; mi < 4; mi++) {
                int r0 = row0 + wm * 64 + mi * 16 + lr;
                float* q = acc[mi][ni];
                if (r0 < M) {
                    float v0 = q[0] + b0, v1 = q[1] + b1;
                    if (sizeof(OutT) == 2) {
                        __half2 h = __floats2half2_rn(v0, v1);
                        *(uint32_t*)((__half*)C + (size_t)r0 * N + col) = *(uint32_t*)&h;
                    } else {
                        *(float2*)((float*)C + (size_t)r0 * N + col) = make_float2(v0, v1);
                    }
                }
                if (r0 + 8 < M) {
                    float v0 = q[2] + b0, v1 = q[3] + b1;
                    if (sizeof(OutT) == 2) {
                        __half2 h = __floats2half2_rn(v0, v1);
                        *(uint32_t*)((__half*)C + (size_t)(r0 + 8) * N + col) = *(uint32_t*)&h;
                    } else {
                        *(float2*)((float*)C + (size_t)(r0 + 8) * N + col) = make_float2(v0, v1);
                    }
                }
            }
        }
    }
}

// ---------------- LayerNorm + ReLU (fp16 in, fp16 out) — layer 1 ----------
__global__ void ln_relu_kernel(const __half* __restrict__ H,
                               const float* __restrict__ gam,
                               const float* __restrict__ bet,
                               __half* __restrict__ out)
{
    int row = blockIdx.x;
    int t   = threadIdx.x;
    uint2 u = *(const uint2*)(H + (size_t)row * DH + t * 4);
    float2 f0 = __half22float2(*(const __half2*)&u.x);
    float2 f1 = __half22float2(*(const __half2*)&u.y);
    float vx = f0.x, vy = f0.y, vz = f1.x, vw = f1.y;
    float s  = vx + vy + vz + vw;
    float ss = vx * vx + vy * vy + vz * vz + vw * vw;
    #pragma unroll
    for (int off = 16; off; off >>= 1) {
        s  += __shfl_down_sync(0xffffffffu, s,  off);
        ss += __shfl_down_sync(0xffffffffu, ss, off);
    }
    __shared__ float sh_s[4], sh_ss[4];
    int w = t >> 5, l = t & 31;
    if (l == 0) { sh_s[w] = s; sh_ss[w] = ss; }
    __syncthreads();
    if (t == 0) {
        float S  = sh_s[0]  + sh_s[1]  + sh_s[2]  + sh_s[3];
        float SS = sh_ss[0] + sh_ss[1] + sh_ss[2] + sh_ss[3];
        float mean = S * (1.0f / DH);
        float var  = SS * (1.0f / DH) - mean * mean;
        sh_s[0]  = mean;
        sh_ss[0] = rsqrtf(var + 1e-5f);
    }
    __syncthreads();
    float mean = sh_s[0], r = sh_ss[0];
    float4 gv = *(const float4*)(gam + t * 4);
    float4 bv = *(const float4*)(bet + t * 4);
    float ox = fmaxf((vx - mean) * r * gv.x + bv.x, 0.f);
    float oy = fmaxf((vy - mean) * r * gv.y + bv.y, 0.f);
    float oz = fmaxf((vz - mean) * r * gv.z + bv.z, 0.f);
    float ow = fmaxf((vw - mean) * r * gv.w + bv.w, 0.f);
    __half2 h0 = __floats2half2_rn(ox, oy);
    __half2 h1 = __floats2half2_rn(oz, ow);
    uint2 o;
    o.x = *(uint32_t*)&h0;
    o.y = *(uint32_t*)&h1;
    *(uint2*)(out + (size_t)row * DH + t * 4) = o;
}

// ---------------- LN2 stats: one warp per row -> (mean, rstd) --------------
__global__ void ln_stats_kernel(const __half* __restrict__ H, float* __restrict__ stats)
{
    int gw   = (blockIdx.x * blockDim.x + threadIdx.x) >> 5;
    if (gw >= NN) return;
    int lane = threadIdx.x & 31;
    const uint4* p = (const uint4*)(H + (size_t)gw * DH) + lane * 2;
    uint4 ua = __ldg(p);
    uint4 ub = __ldg(p + 1);
    float s = 0.f, ss = 0.f;
    const uint32_t* pa = &ua.x;
    const uint32_t* pb = &ub.x;
    #pragma unroll
    for (int q = 0; q < 4; q++) {
        float2 f = __half22float2(*(const __half2*)&pa[q]);
        float2 g = __half22float2(*(const __half2*)&pb[q]);
        s  += f.x + f.y + g.x + g.y;
        ss += f.x * f.x + f.y * f.y + g.x * g.x + g.y * g.y;
    }
    #pragma unroll
    for (int off = 16; off; off >>= 1) {
        s  += __shfl_xor_sync(0xffffffffu, s,  off);
        ss += __shfl_xor_sync(0xffffffffu, ss, off);
    }
    if (lane == 0) {
        float mean = s * (1.0f / DH);
        float var  = ss * (1.0f / DH) - mean * mean;
        ((float2*)stats)[gw] = make_float2(mean, rsqrtf(var + 1e-5f));
    }
}

// ---------------- classifier GEMM with fused LN2+ReLU on A ----------------
// BM=64, BN=128 (=NCLS), K=512, 256 thr (8 warps 2x4, warp tile 32x32).
// A staged from pre16 via registers with LN applied; B via cp.async.
__global__ void __launch_bounds__(256, 2)
cls_mma_ln(const __half* __restrict__ PRE, const float* __restrict__ stats,
           const float* __restrict__ gam, const float* __restrict__ bet,
           const __half* __restrict__ W, const float* __restrict__ bias,
           float* __restrict__ C, int M)
{
    extern __shared__ __align__(1024) char smem[];
    const uint32_t sbase = (uint32_t)__cvta_generic_to_shared(smem);
    const uint32_t ABYTES = 8192;                 // 64 rows x 128B
    const uint32_t BOFF   = 2 * ABYTES;           // B after 2 A buffers
    const uint32_t BBYTES = 16384;                // 128 rows x 128B

    const int tid = threadIdx.x;
    const int wid = tid >> 5, lid = tid & 31;
    const int wm = wid & 1, wn = wid >> 1;        // 2 x 4 warp grid
    const int row0 = blockIdx.x * 64;
    const int nch = DH / 64;                      // 8

    // A staging geometry: thread covers row (tid>>2), 16 cols at (tid&3)*16
    const int ar   = row0 + (tid >> 2);
    const bool av  = ar < M;
    const int acg  = (tid & 3) * 16;              // col offset within chunk
    float mean = 0.f, rstd = 1.f;
    if (av) {
        float2 st = __ldg((const float2*)stats + ar);
        mean = st.x; rstd = st.y;
    }

    float acc[2][4][4];
    #pragma unroll
    for (int i = 0; i < 2; i++)
        #pragma unroll
        for (int j = 0; j < 4; j++)
            #pragma unroll
            for (int q = 0; q < 4; q++) acc[i][j][q] = 0.f;

    // load + LN one A chunk into regs (2 x uint4 packed halves)
    uint4 pa0, pa1;
    auto ldg_a = [&](int c) {
        int kc = c * 64 + acg;
        if (av) {
            const uint4* p = (const uint4*)(PRE + (size_t)ar * DH + kc);
            uint4 ua = __ldg(p);
            uint4 ub = __ldg(p + 1);
            float gb[16], bb[16];
            #pragma unroll
            for (int q = 0; q < 4; q++) {
                *(float4*)&gb[q * 4] = __ldg((const float4*)(gam + kc) + q);
                *(float4*)&bb[q * 4] = __ldg((const float4*)(bet + kc) + q);
            }
            const uint32_t* ia = &ua.x;
            const uint32_t* ib = &ub.x;
            uint32_t* oa = &pa0.x;
            uint32_t* ob = &pa1.x;
            #pragma unroll
            for (int q = 0; q < 4; q++) {
                float2 f = __half22float2(*(const __half2*)&ia[q]);
                float y0 = fmaxf((f.x - mean) * rstd * gb[q * 2 + 0] + bb[q * 2 + 0], 0.f);
                float y1 = fmaxf((f.y - mean) * rstd * gb[q * 2 + 1] + bb[q * 2 + 1], 0.f);
                __half2 h = __floats2half2_rn(y0, y1);
                oa[q] = *(uint32_t*)&h;
                float2 g = __half22float2(*(const __half2*)&ib[q]);
                float z0 = fmaxf((g.x - mean) * rstd * gb[8 + q * 2 + 0] + bb[8 + q * 2 + 0], 0.f);
                float z1 = fmaxf((g.y - mean) * rstd * gb[8 + q * 2 + 1] + bb[8 + q * 2 + 1], 0.f);
                __half2 h2 = __floats2half2_rn(z0, z1);
                ob[q] = *(uint32_t*)&h2;
            }
        } else {
            pa0 = make_uint4(0, 0, 0, 0);
            pa1 = make_uint4(0, 0, 0, 0);
        }
    };

    auto ldb = [&](int c, int buf) {
        const int k0 = c * 64;
        const uint32_t sbb = sbase + BOFF + (uint32_t)buf * BBYTES;
        int G = tid;
        #pragma unroll
        for (int rep = 0; rep < 4; rep++, G += 256) {
            int row = G >> 3, g = G & 7;
            cp16(sbb + SWZ((uint32_t)row * 128 + g * 16),
                 W + (size_t)row * DH + k0 + g * 8, true);
        }
        asm volatile("cp.async.commit_group;" ::: "memory");
    };

    ldg_a(0);
    ldb(0, 0);
    for (int c = 0; c < nch; c++) {
        const int buf = c & 1;
        // store staged A regs
        {
            uint32_t sa = sbase + (uint32_t)buf * ABYTES
                        + SWZ((uint32_t)(tid >> 2) * 128 + (uint32_t)acg * 2);
            *(uint4*)(smem + (sa - sbase)) = pa0;
            *(uint4*)(smem + (SWZ((uint32_t)(tid >> 2) * 128 + (uint32_t)acg * 2 + 16)
                              + (uint32_t)buf * ABYTES)) = pa1;
        }
        if (c + 1 < nch) {
            ldb(c + 1, (c + 1) & 1);
            ldg_a(c + 1);
            asm volatile("cp.async.wait_group 1;" ::: "memory");
        } else {
            asm volatile("cp.async.wait_group 0;" ::: "memory");
        }
        __syncthreads();

        const uint32_t ca = sbase + (uint32_t)buf * ABYTES;
        const uint32_t cb = sbase + BOFF + (uint32_t)buf * BBYTES;
        #pragma unroll
        for (int kb = 0; kb < 4; kb++) {
            uint32_t a[2][4], b[4][2];
            #pragma unroll
            for (int mi = 0; mi < 2; mi++) {
                uint32_t r = (uint32_t)(wm * 32 + mi * 16 + (lid & 15));
                ldsm_x4u(a[mi], ca + SWZ(r * 128 + kb * 32 + (lid >> 4) * 16));
            }
            #pragma unroll
            for (int ni = 0; ni < 4; ni++) {
                uint32_t n = (uint32_t)(wn * 32 + ni * 8 + (lid & 7));
                ldsm_x2u(b[ni], cb + SWZ(n * 128 + kb * 32 + ((lid >> 3) & 1) * 16));
            }
            #pragma unroll
            for (int mi = 0; mi < 2; mi++)
                #pragma unroll
                for (int ni = 0; ni < 4; ni++)
                    mma16816(acc[mi][ni], a[mi], b[ni]);
        }
        __syncthreads();
    }

    // epilogue: bias + store fp32
    {
        const int lr = lid >> 2;
        const int lc = (lid & 3) * 2;
        #pragma unroll
        for (int ni = 0; ni < 4; ni++) {
            int col = wn * 32 + ni * 8 + lc;
            float b0 = bias[col], b1 = bias[col + 1];
            #pragma unroll
            for (int mi = 0; mi < 2; mi++) {
                int r0 = row0 + wm * 32 + mi * 16 + lr;
                float* q = acc[mi][ni];
                if (r0 < M)
                    *(float2*)(C + (size_t)r0 * NCLS + col) = make_float2(q[0] + b0, q[1] + b1);
                if (r0 + 8 < M)
                    *(float2*)(C + (size_t)(r0 + 8) * NCLS + col) = make_float2(q[2] + b0, q[3] + b1);
            }
        }
    }
}

// ---------------- launch --------------------------------------------------
extern "C" void kernel_launch(void* const* d_in, const int* in_sizes, int n_in,
                              void* d_out, int out_size)
{
    const float* x      = (const float*)d_in[0];
    const int*   ei     = (const int*)  d_in[1];
    const float* Wrel1  = (const float*)d_in[3];
    const float* brel1  = (const float*)d_in[4];
    const float* Wroot1 = (const float*)d_in[5];
    const float* g1     = (const float*)d_in[6];
    const float* b1     = (const float*)d_in[7];
    const float* Wrel2  = (const float*)d_in[8];
    const float* brel2  = (const float*)d_in[9];
    const float* Wroot2 = (const float*)d_in[10];
    const float* g2     = (const float*)d_in[11];
    const float* b2     = (const float*)d_in[12];
    const float* Wcls   = (const float*)d_in[13];
    const float* bcls   = (const float*)d_in[14];
    float* out = (float*)d_out;

    const int* src = ei;
    const int* dst = ei + EE;

    __half *pre16, *x16, *agg16, *h16, *w16;
    float  *stats;
    cudaGetSymbolAddress((void**)&pre16, g_pre16);
    cudaGetSymbolAddress((void**)&x16,   g_x16);
    cudaGetSymbolAddress((void**)&agg16, g_agg16);
    cudaGetSymbolAddress((void**)&h16,   g_h16);
    cudaGetSymbolAddress((void**)&w16,   g_w16);
    cudaGetSymbolAddress((void**)&stats, g_stats);

    __half* wrel1_16  = w16;
    __half* wroot1_16 = w16 + 65536;
    __half* wrel2_16  = w16 + 131072;
    __half* wroot2_16 = w16 + 393216;
    __half* wcls_16   = w16 + 655360;

    const int SMEM_G = 4 * 16384;                 // 65536
    const int SMEM_C = 2 * 8192 + 2 * 16384;      // 49152
    cudaFuncSetAttribute((const void*)mma_dual<__half>,
                         cudaFuncAttributeMaxDynamicSharedMemorySize, SMEM_G);
    cudaFuncSetAttribute((const void*)cls_mma_ln,
                         cudaFuncAttributeMaxDynamicSharedMemorySize, SMEM_C);

    f2h_zero_kernel<<<(1780224 + NN + 255) / 256, 256>>>(
        x, Wrel1, Wroot1, Wrel2, Wroot2, Wcls, x16, w16);
    hist_kernel       <<<(EE + 255) / 256, 256>>>(dst);
    deg_partial_kernel<<<NBLK, 256>>>();
    scan_apply_kernel <<<NBLK, 256>>>();
    scatter_kernel    <<<(EE + 255) / 256, 256>>>(src, dst);

    const int MT = (NN + 127) / 128;              // 391
    dim3 gemm_h(DH / 128, MT);                    // (4, 391)

    // Layer 1
    gather_max_kernel<DIN><<<(NN * (DIN / 16) + 255) / 256, 256>>>(x16, agg16);
    mma_dual<__half><<<gemm_h, 256, SMEM_G>>>(
        agg16, wrel1_16, DIN, x16, wroot1_16, DIN, brel1, pre16, NN, DH);
    ln_relu_kernel<<<NN, 128>>>(pre16, g1, b1, h16);

    // Layer 2
    gather_max_kernel<DH><<<(NN * (DH / 16) + 255) / 256, 256>>>(h16, agg16);
    mma_dual<__half><<<gemm_h, 256, SMEM_G>>>(
        agg16, wrel2_16, DH, h16, wroot2_16, DH, brel2, pre16, NN, DH);

    // LN2 stats + fused classifier
    ln_stats_kernel<<<(NN * 32 + 255) / 256, 256>>>(pre16, stats);
    cls_mma_ln<<<(NN + 63) / 64, 256, SMEM_C>>>(
        pre16, stats, g2, b2, wcls_16, bcls, out, NN);
}

// round 14
// speedup vs baseline: 1.0283x; 1.0283x over previous
#include <cuda_runtime.h>
#include <cuda_fp16.h>
#include <cstdint>

#define NN   50000
#define EE   400000
#define DIN  128
#define DH   512
#define NCLS 128
#define NBLK 196   // (NN + 255) / 256
#define PCTAS 296  // 2 CTAs/SM x 148 SMs

// ---------------- scratch (allocation-free: device globals) ----------------
__device__ __half g_pre16[(size_t)NN * DH];
__device__ __half g_x16 [(size_t)NN * DIN];
__device__ __half g_agg16[(size_t)NN * DH];
__device__ __half g_h16 [(size_t)NN * DH];
__device__ __half g_w16 [720896];     // Wrel1|Wroot1|Wrel2|Wroot2|Wcls
__device__ int    g_deg[NN];
__device__ int    g_part[256];
__device__ int    g_rowptr[NN + 1];
__device__ int    g_cursor[NN];
__device__ int    g_csrc[EE];
__device__ float  g_cew [EE];

#define SWZ(x) ((x) ^ (((x) >> 3) & 0x70))

// ---------------- fused fp32->fp16 conversions + zero_deg ----------------
__global__ void f2h_zero_kernel(const float* __restrict__ x,
                                const float* __restrict__ Wrel1,
                                const float* __restrict__ Wroot1,
                                const float* __restrict__ Wrel2,
                                const float* __restrict__ Wroot2,
                                const float* __restrict__ Wcls,
                                __half* __restrict__ x16,
                                __half* __restrict__ w16)
{
    int gid = blockIdx.x * blockDim.x + threadIdx.x;
    if (gid >= 1780224) {
        int z = gid - 1780224;
        if (z < NN) g_deg[z] = 0;
        return;
    }
    const float* src;
    __half* dst;
    int i = gid;
    if (i < 1600000)        { src = x;      dst = x16;          }
    else if (i < 1616384)   { src = Wrel1;  dst = w16;          i -= 1600000; }
    else if (i < 1632768)   { src = Wroot1; dst = w16 + 65536;  i -= 1616384; }
    else if (i < 1698304)   { src = Wrel2;  dst = w16 + 131072; i -= 1632768; }
    else if (i < 1763840)   { src = Wroot2; dst = w16 + 393216; i -= 1698304; }
    else                    { src = Wcls;   dst = w16 + 655360; i -= 1763840; }
    float4 v = ((const float4*)src)[i];
    __half2 h0 = __floats2half2_rn(v.x, v.y);
    __half2 h1 = __floats2half2_rn(v.z, v.w);
    uint2 u;
    u.x = *(uint32_t*)&h0;
    u.y = *(uint32_t*)&h1;
    ((uint2*)dst)[i] = u;
}

// ---------------- CSR build ----------------
__global__ void hist_kernel(const int* __restrict__ dst) {
    int e = blockIdx.x * blockDim.x + threadIdx.x;
    if (e < EE) atomicAdd(&g_deg[dst[e]], 1);
}

__global__ void deg_partial_kernel() {
    int i = blockIdx.x * 256 + threadIdx.x;
    int v = (i < NN) ? g_deg[i] : 0;
    int lane = threadIdx.x & 31, w = threadIdx.x >> 5;
    #pragma unroll
    for (int off = 16; off; off >>= 1)
        v += __shfl_down_sync(0xffffffffu, v, off);
    __shared__ int ws[8];
    if (lane == 0) ws[w] = v;
    __syncthreads();
    if (threadIdx.x == 0) {
        int t = 0;
        #pragma unroll
        for (int q = 0; q < 8; q++) t += ws[q];
        g_part[blockIdx.x] = t;
    }
}

__global__ void scan_apply_kernel() {
    __shared__ int part[256];
    __shared__ int wsum[8];
    int t = threadIdx.x;
    part[t] = (t < NBLK) ? g_part[t] : 0;
    __syncthreads();
    #pragma unroll
    for (int off = 1; off < 256; off <<= 1) {
        int tv = (t >= off) ? part[t - off] : 0;
        __syncthreads();
        part[t] += tv;
        __syncthreads();
    }
    int blockoff = (blockIdx.x > 0) ? part[blockIdx.x - 1] : 0;

    int i = blockIdx.x * 256 + t;
    int d = (i < NN) ? g_deg[i] : 0;
    int lane = t & 31, w = t >> 5;
    int v = d;
    #pragma unroll
    for (int off = 1; off < 32; off <<= 1) {
        int u = __shfl_up_sync(0xffffffffu, v, off);
        if (lane >= off) v += u;
    }
    if (lane == 31) wsum[w] = v;
    __syncthreads();
    if (w == 0) {
        int x = (lane < 8) ? wsum[lane] : 0;
        #pragma unroll
        for (int off = 1; off < 8; off <<= 1) {
            int u = __shfl_up_sync(0xffffffffu, x, off);
            if (lane >= off) x += u;
        }
        if (lane < 8) wsum[lane] = x;
    }
    __syncthreads();
    int excl = (v - d) + (w > 0 ? wsum[w - 1] : 0) + blockoff;
    if (i < NN) {
        g_cursor[i]     = excl;
        g_rowptr[i + 1] = excl + d;
    }
    if (i == 0) g_rowptr[0] = 0;
}

__global__ void scatter_kernel(const int* __restrict__ src, const int* __restrict__ dst) {
    int e = blockIdx.x * blockDim.x + threadIdx.x;
    if (e >= EE) return;
    int s = src[e], d = dst[e];
    int p = atomicAdd(&g_cursor[d], 1);
    g_csrc[p] = s;
    g_cew[p] = 1.0f / (float)(s - d);   // pos = arange: exact in fp32
}

// ---------------- segment-max via gather (R12) ----------
template <int D>
__global__ void gather_max_kernel(const __half* __restrict__ X, __half* __restrict__ out) {
    const int TPN = D / 16;
    int gid  = blockIdx.x * blockDim.x + threadIdx.x;
    int node = gid / TPN;
    int lane = gid % TPN;
    if (node >= NN) return;
    int s = g_rowptr[node];
    int e = g_rowptr[node + 1];
    const float NEG = -3.402823466e+38f;
    float acc[16];
    #pragma unroll
    for (int q = 0; q < 16; q++) acc[q] = NEG;

    int   sn0 = 0, sn1 = 0;
    float ew0 = 0.f, ew1 = 0.f;
    if (s + 1 < e) {
        sn0 = g_csrc[s];     sn1 = g_csrc[s + 1];
        ew0 = g_cew[s];      ew1 = g_cew[s + 1];
    }

    int j = s;
    for (; j + 1 < e; j += 2) {
        float cw0 = ew0, cw1 = ew1;
        const uint4* r0 = (const uint4*)(X + (size_t)sn0 * D) + lane * 2;
        const uint4* r1 = (const uint4*)(X + (size_t)sn1 * D) + lane * 2;
        uint4 u0a = __ldg(r0);
        uint4 u0b = __ldg(r0 + 1);
        uint4 u1a = __ldg(r1);
        uint4 u1b = __ldg(r1 + 1);
        int nj = j + 2;
        if (nj + 1 < e) {
            sn0 = g_csrc[nj];     sn1 = g_csrc[nj + 1];
            ew0 = g_cew[nj];      ew1 = g_cew[nj + 1];
        }
        const uint32_t* p0a = &u0a.x;
        const uint32_t* p0b = &u0b.x;
        const uint32_t* p1a = &u1a.x;
        const uint32_t* p1b = &u1b.x;
        #pragma unroll
        for (int q = 0; q < 4; q++) {
            float2 f0 = __half22float2(*(const __half2*)&p0a[q]);
            float2 f1 = __half22float2(*(const __half2*)&p1a[q]);
            acc[q * 2 + 0] = fmaxf(acc[q * 2 + 0], fmaxf(f0.x * cw0, f1.x * cw1));
            acc[q * 2 + 1] = fmaxf(acc[q * 2 + 1], fmaxf(f0.y * cw0, f1.y * cw1));
            float2 g0 = __half22float2(*(const __half2*)&p0b[q]);
            float2 g1 = __half22float2(*(const __half2*)&p1b[q]);
            acc[8 + q * 2 + 0] = fmaxf(acc[8 + q * 2 + 0], fmaxf(g0.x * cw0, g1.x * cw1));
            acc[8 + q * 2 + 1] = fmaxf(acc[8 + q * 2 + 1], fmaxf(g0.y * cw0, g1.y * cw1));
        }
    }
    if (j < e) {
        int   sn = g_csrc[j];
        float ew = g_cew[j];
        const uint4* r = (const uint4*)(X + (size_t)sn * D) + lane * 2;
        uint4 ua = __ldg(r);
        uint4 ub = __ldg(r + 1);
        const uint32_t* pa = &ua.x;
        const uint32_t* pb = &ub.x;
        #pragma unroll
        for (int q = 0; q < 4; q++) {
            float2 f = __half22float2(*(const __half2*)&pa[q]);
            acc[q * 2 + 0] = fmaxf(acc[q * 2 + 0], f.x * ew);
            acc[q * 2 + 1] = fmaxf(acc[q * 2 + 1], f.y * ew);
            float2 g = __half22float2(*(const __half2*)&pb[q]);
            acc[8 + q * 2 + 0] = fmaxf(acc[8 + q * 2 + 0], g.x * ew);
            acc[8 + q * 2 + 1] = fmaxf(acc[8 + q * 2 + 1], g.y * ew);
        }
    }
    if (e == s) {
        #pragma unroll
        for (int q = 0; q < 16; q++) acc[q] = 0.f;
    }
    uint4 oa, ob;
    uint32_t* pa = &oa.x;
    uint32_t* pb = &ob.x;
    #pragma unroll
    for (int q = 0; q < 4; q++) {
        __half2 h0 = __floats2half2_rn(acc[q * 2],     acc[q * 2 + 1]);
        __half2 h1 = __floats2half2_rn(acc[8 + q * 2], acc[8 + q * 2 + 1]);
        pa[q] = *(uint32_t*)&h0;
        pb[q] = *(uint32_t*)&h1;
    }
    uint4* op = (uint4*)(out + (size_t)node * D) + lane * 2;
    op[0] = oa;
    op[1] = ob;
}

// ---------------- MMA helpers ----------------
__device__ __forceinline__ void mma16816(float* d, const uint32_t* a, const uint32_t* b) {
    asm volatile(
        "mma.sync.aligned.m16n8k16.row.col.f32.f16.f16.f32 "
        "{%0,%1,%2,%3}, {%4,%5,%6,%7}, {%8,%9}, {%0,%1,%2,%3};"
        : "+f"(d[0]), "+f"(d[1]), "+f"(d[2]), "+f"(d[3])
        : "r"(a[0]), "r"(a[1]), "r"(a[2]), "r"(a[3]), "r"(b[0]), "r"(b[1]));
}
__device__ __forceinline__ void ldsm_x4u(uint32_t* r, uint32_t a) {
    asm volatile("ldmatrix.sync.aligned.m8n8.x4.shared.b16 {%0,%1,%2,%3}, [%4];"
                 : "=r"(r[0]), "=r"(r[1]), "=r"(r[2]), "=r"(r[3]) : "r"(a));
}
__device__ __forceinline__ void ldsm_x2u(uint32_t* r, uint32_t a) {
    asm volatile("ldmatrix.sync.aligned.m8n8.x2.shared.b16 {%0,%1}, [%2];"
                 : "=r"(r[0]), "=r"(r[1]) : "r"(a));
}
__device__ __forceinline__ void cp16(uint32_t dst, const void* src, bool v) {
    int sz = v ? 16 : 0;
    asm volatile("cp.async.cg.shared.global [%0], [%1], 16, %2;"
                 :: "r"(dst), "l"(src), "r"(sz));
}

// ------- persistent fp16 mma.sync dual-GEMM: 128x128 tiles, 2 CTA/SM -------
template <typename OutT>
__global__ void __launch_bounds__(256, 2)
mma_dual(const __half* __restrict__ A1, const __half* __restrict__ W1, int K1,
         const __half* __restrict__ A2, const __half* __restrict__ W2, int K2,
         const float* __restrict__ bias, OutT* __restrict__ C, int M, int N)
{
    extern __shared__ __align__(1024) char smem[];
    const uint32_t sbase = (uint32_t)__cvta_generic_to_shared(smem);
    const uint32_t ABYTES = 16384;
    const uint32_t BBYTES = 16384;

    const int tid = threadIdx.x;
    const int wid = tid >> 5, lid = tid & 31;
    const int wm = wid & 1, wn = wid >> 1;
    const int NX = N >> 7;
    const int ntiles = ((M + 127) >> 7) * NX;

    const int nc1 = K1 / 64;
    const int nc2 = A2 ? (K2 / 64) : 0;
    const int nch = nc1 + nc2;

    int t = blockIdx.x;
    if (t >= ntiles) return;
    int row0 = (t / NX) << 7;
    int col0 = (t % NX) << 7;

    auto load_chunk = [&](int c, int buf, int r0, int c0) {
        const int pass = (c >= nc1);
        const __half* A = pass ? A2 : A1;
        const __half* W = pass ? W2 : W1;
        const int K  = pass ? K2 : K1;
        const int k0 = (pass ? (c - nc1) : c) * 64;
        const uint32_t sa  = sbase + (uint32_t)buf * ABYTES;
        const uint32_t sbb = sbase + 2 * ABYTES + (uint32_t)buf * BBYTES;
        int G = tid;
        #pragma unroll
        for (int rep = 0; rep < 4; rep++, G += 256) {
            int row = G >> 3, g = G & 7;
            bool v = (r0 + row) < M;
            size_t r = v ? (size_t)(r0 + row) : 0;
            cp16(sa + SWZ((uint32_t)row * 128 + g * 16), A + r * K + k0 + g * 8, v);
        }
        G = tid;
        #pragma unroll
        for (int rep = 0; rep < 4; rep++, G += 256) {
            int row = G >> 3, g = G & 7;
            cp16(sbb + SWZ((uint32_t)row * 128 + g * 16),
                 W + (size_t)(c0 + row) * K + k0 + g * 8, true);
        }
        asm volatile("cp.async.commit_group;" ::: "memory");
    };

    float acc[4][4][4];
    #pragma unroll
    for (int i = 0; i < 4; i++)
        #pragma unroll
        for (int j = 0; j < 4; j++)
            #pragma unroll
            for (int q = 0; q < 4; q++) acc[i][j][q] = 0.f;

    int buf = 0;
    load_chunk(0, 0, row0, col0);

    while (true) {
        const int nt = t + gridDim.x;
        const bool have_next = nt < ntiles;
        const int nrow0 = have_next ? ((nt / NX) << 7) : 0;
        const int ncol0 = have_next ? ((nt % NX) << 7) : 0;

        for (int c = 0; c < nch; c++) {
            if (c + 1 < nch) {
                load_chunk(c + 1, buf ^ 1, row0, col0);
                asm volatile("cp.async.wait_group 1;" ::: "memory");
            } else if (have_next) {
                load_chunk(0, buf ^ 1, nrow0, ncol0);
                asm volatile("cp.async.wait_group 1;" ::: "memory");
            } else {
                asm volatile("cp.async.wait_group 0;" ::: "memory");
            }
            __syncthreads();

            const uint32_t ca = sbase + (uint32_t)buf * ABYTES;
            const uint32_t cb = sbase + 2 * ABYTES + (uint32_t)buf * BBYTES;
            #pragma unroll
            for (int kb = 0; kb < 4; kb++) {
                uint32_t a[4][4], b[4][2];
                #pragma unroll
                for (int mi = 0; mi < 4; mi++) {
                    uint32_t r = (uint32_t)(wm * 64 + mi * 16 + (lid & 15));
                    ldsm_x4u(a[mi], ca + SWZ(r * 128 + kb * 32 + (lid >> 4) * 16));
                }
                #pragma unroll
                for (int ni = 0; ni < 4; ni++) {
                    uint32_t n = (uint32_t)(wn * 32 + ni * 8 + (lid & 7));
                    ldsm_x2u(b[ni], cb + SWZ(n * 128 + kb * 32 + ((lid >> 3) & 1) * 16));
                }
                #pragma unroll
                for (int mi = 0; mi < 4; mi++)
                    #pragma unroll
                    for (int ni = 0; ni < 4; ni++)
                        mma16816(acc[mi][ni], a[mi], b[ni]);
            }
            __syncthreads();
            buf ^= 1;
        }

        // ---- epilogue (registers + gmem only; overlaps next tile's load) ----
        {
            const int lr = lid >> 2;
            const int lc = (lid & 3) * 2;
            #pragma unroll
            for (int ni = 0; ni < 4; ni++) {
                int col = col0 + wn * 32 + ni * 8 + lc;
                float b0 = bias[col], b1 = bias[col + 1];
                #pragma unroll
                for (int mi = 0; mi < 4; mi++) {
                    int r0 = row0 + wm * 64 + mi * 16 + lr;
                    float* q = acc[mi][ni];
                    if (r0 < M) {
                        float v0 = q[0] + b0, v1 = q[1] + b1;
                        if (sizeof(OutT) == 2) {
                            __half2 h = __floats2half2_rn(v0, v1);
                            *(uint32_t*)((__half*)C + (size_t)r0 * N + col) = *(uint32_t*)&h;
                        } else {
                            *(float2*)((float*)C + (size_t)r0 * N + col) = make_float2(v0, v1);
                        }
                    }
                    if (r0 + 8 < M) {
                        float v0 = q[2] + b0, v1 = q[3] + b1;
                        if (sizeof(OutT) == 2) {
                            __half2 h = __floats2half2_rn(v0, v1);
                            *(uint32_t*)((__half*)C + (size_t)(r0 + 8) * N + col) = *(uint32_t*)&h;
                        } else {
                            *(float2*)((float*)C + (size_t)(r0 + 8) * N + col) = make_float2(v0, v1);
                        }
                    }
                }
            }
        }

        if (!have_next) break;
        t = nt; row0 = nrow0; col0 = ncol0;
        #pragma unroll
        for (int i = 0; i < 4; i++)
            #pragma unroll
            for (int j = 0; j < 4; j++)
                #pragma unroll
                for (int q = 0; q < 4; q++) acc[i][j][q] = 0.f;
    }
}

// ---------------- LayerNorm + ReLU (fp16 in, fp16 out) ----------
__global__ void ln_relu_kernel(const __half* __restrict__ H,
                               const float* __restrict__ gam,
                               const float* __restrict__ bet,
                               __half* __restrict__ out)
{
    int row = blockIdx.x;
    int t   = threadIdx.x;
    uint2 u = *(const uint2*)(H + (size_t)row * DH + t * 4);
    float2 f0 = __half22float2(*(const __half2*)&u.x);
    float2 f1 = __half22float2(*(const __half2*)&u.y);
    float vx = f0.x, vy = f0.y, vz = f1.x, vw = f1.y;
    float s  = vx + vy + vz + vw;
    float ss = vx * vx + vy * vy + vz * vz + vw * vw;
    #pragma unroll
    for (int off = 16; off; off >>= 1) {
        s  += __shfl_down_sync(0xffffffffu, s,  off);
        ss += __shfl_down_sync(0xffffffffu, ss, off);
    }
    __shared__ float sh_s[4], sh_ss[4];
    int w = t >> 5, l = t & 31;
    if (l == 0) { sh_s[w] = s; sh_ss[w] = ss; }
    __syncthreads();
    if (t == 0) {
        float S  = sh_s[0]  + sh_s[1]  + sh_s[2]  + sh_s[3];
        float SS = sh_ss[0] + sh_ss[1] + sh_ss[2] + sh_ss[3];
        float mean = S * (1.0f / DH);
        float var  = SS * (1.0f / DH) - mean * mean;
        sh_s[0]  = mean;
        sh_ss[0] = rsqrtf(var + 1e-5f);
    }
    __syncthreads();
    float mean = sh_s[0], r = sh_ss[0];
    float4 gv = *(const float4*)(gam + t * 4);
    float4 bv = *(const float4*)(bet + t * 4);
    float ox = fmaxf((vx - mean) * r * gv.x + bv.x, 0.f);
    float oy = fmaxf((vy - mean) * r * gv.y + bv.y, 0.f);
    float oz = fmaxf((vz - mean) * r * gv.z + bv.z, 0.f);
    float ow = fmaxf((vw - mean) * r * gv.w + bv.w, 0.f);
    __half2 h0 = __floats2half2_rn(ox, oy);
    __half2 h1 = __floats2half2_rn(oz, ow);
    uint2 o;
    o.x = *(uint32_t*)&h0;
    o.y = *(uint32_t*)&h1;
    *(uint2*)(out + (size_t)row * DH + t * 4) = o;
}

// ---------------- launch --------------------------------------------------
extern "C" void kernel_launch(void* const* d_in, const int* in_sizes, int n_in,
                              void* d_out, int out_size)
{
    const float* x      = (const float*)d_in[0];
    const int*   ei     = (const int*)  d_in[1];
    const float* Wrel1  = (const float*)d_in[3];
    const float* brel1  = (const float*)d_in[4];
    const float* Wroot1 = (const float*)d_in[5];
    const float* g1     = (const float*)d_in[6];
    const float* b1     = (const float*)d_in[7];
    const float* Wrel2  = (const float*)d_in[8];
    const float* brel2  = (const float*)d_in[9];
    const float* Wroot2 = (const float*)d_in[10];
    const float* g2     = (const float*)d_in[11];
    const float* b2     = (const float*)d_in[12];
    const float* Wcls   = (const float*)d_in[13];
    const float* bcls   = (const float*)d_in[14];
    float* out = (float*)d_out;

    const int* src = ei;
    const int* dst = ei + EE;

    __half *pre16, *x16, *agg16, *h16, *w16;
    cudaGetSymbolAddress((void**)&pre16, g_pre16);
    cudaGetSymbolAddress((void**)&x16,   g_x16);
    cudaGetSymbolAddress((void**)&agg16, g_agg16);
    cudaGetSymbolAddress((void**)&h16,   g_h16);
    cudaGetSymbolAddress((void**)&w16,   g_w16);

    __half* wrel1_16  = w16;
    __half* wroot1_16 = w16 + 65536;
    __half* wrel2_16  = w16 + 131072;
    __half* wroot2_16 = w16 + 393216;
    __half* wcls_16   = w16 + 655360;

    const int SMEM_G = 4 * 16384;   // 65536
    cudaFuncSetAttribute((const void*)mma_dual<__half>,
                         cudaFuncAttributeMaxDynamicSharedMemorySize, SMEM_G);
    cudaFuncSetAttribute((const void*)mma_dual<float>,
                         cudaFuncAttributeMaxDynamicSharedMemorySize, SMEM_G);

    f2h_zero_kernel<<<(1780224 + NN + 255) / 256, 256>>>(
        x, Wrel1, Wroot1, Wrel2, Wroot2, Wcls, x16, w16);
    hist_kernel       <<<(EE + 255) / 256, 256>>>(dst);
    deg_partial_kernel<<<NBLK, 256>>>();
    scan_apply_kernel <<<NBLK, 256>>>();
    scatter_kernel    <<<(EE + 255) / 256, 256>>>(src, dst);

    // Layer 1
    gather_max_kernel<DIN><<<(NN * (DIN / 16) + 255) / 256, 256>>>(x16, agg16);
    mma_dual<__half><<<PCTAS, 256, SMEM_G>>>(
        agg16, wrel1_16, DIN, x16, wroot1_16, DIN, brel1, pre16, NN, DH);
    ln_relu_kernel<<<NN, 128>>>(pre16, g1, b1, h16);

    // Layer 2
    gather_max_kernel<DH><<<(NN * (DH / 16) + 255) / 256, 256>>>(h16, agg16);
    mma_dual<__half><<<PCTAS, 256, SMEM_G>>>(
        agg16, wrel2_16, DH, h16, wroot2_16, DH, brel2, pre16, NN, DH);
    ln_relu_kernel<<<NN, 128>>>(pre16, g2, b2, h16);

    // Classifier
    mma_dual<float><<<PCTAS, 256, SMEM_G>>>(
        h16, wcls_16, DH, nullptr, nullptr, 0, bcls, out, NN, NCLS);
}

// round 15
// speedup vs baseline: 1.0478x; 1.0190x over previous
#include <cuda_runtime.h>
#include <cuda_fp16.h>
#include <cstdint>

#define NN   50000
#define EE   400000
#define DIN  128
#define DH   512
#define NCLS 128
#define NBLK 196   // (NN + 255) / 256
#define PCTAS 296  // 2 CTAs/SM x 148 SMs

// ---------------- scratch (allocation-free: device globals) ----------------
__device__ __half g_pre16[(size_t)NN * DH];
__device__ __half g_x16 [(size_t)NN * DIN];
__device__ __half g_agg16[(size_t)NN * DH];
__device__ __half g_h16 [(size_t)NN * DH];
__device__ __half g_w16 [720896];     // Wrel1|Wroot1|Wrel2|Wroot2|Wcls
__device__ int    g_deg[NN];
__device__ int    g_part[256];
__device__ int    g_rowptr[NN + 1];
__device__ int    g_cursor[NN];
__device__ int    g_csrc[EE];
__device__ __half g_cew16[EE];        // 1024/(s-d) in fp16 (normal range)

#define SWZ(x) ((x) ^ (((x) >> 3) & 0x70))

// ---------------- fused fp32->fp16 conversions + zero_deg ----------------
__global__ void f2h_zero_kernel(const float* __restrict__ x,
                                const float* __restrict__ Wrel1,
                                const float* __restrict__ Wroot1,
                                const float* __restrict__ Wrel2,
                                const float* __restrict__ Wroot2,
                                const float* __restrict__ Wcls,
                                __half* __restrict__ x16,
                                __half* __restrict__ w16)
{
    int gid = blockIdx.x * blockDim.x + threadIdx.x;
    if (gid >= 1780224) {
        int z = gid - 1780224;
        if (z < NN) g_deg[z] = 0;
        return;
    }
    const float* src;
    __half* dst;
    int i = gid;
    if (i < 1600000)        { src = x;      dst = x16;          }
    else if (i < 1616384)   { src = Wrel1;  dst = w16;          i -= 1600000; }
    else if (i < 1632768)   { src = Wroot1; dst = w16 + 65536;  i -= 1616384; }
    else if (i < 1698304)   { src = Wrel2;  dst = w16 + 131072; i -= 1632768; }
    else if (i < 1763840)   { src = Wroot2; dst = w16 + 393216; i -= 1698304; }
    else                    { src = Wcls;   dst = w16 + 655360; i -= 1763840; }
    float4 v = ((const float4*)src)[i];
    __half2 h0 = __floats2half2_rn(v.x, v.y);
    __half2 h1 = __floats2half2_rn(v.z, v.w);
    uint2 u;
    u.x = *(uint32_t*)&h0;
    u.y = *(uint32_t*)&h1;
    ((uint2*)dst)[i] = u;
}

// ---------------- CSR build ----------------
__global__ void hist_kernel(const int* __restrict__ dst) {
    int e = blockIdx.x * blockDim.x + threadIdx.x;
    if (e < EE) atomicAdd(&g_deg[dst[e]], 1);
}

__global__ void deg_partial_kernel() {
    int i = blockIdx.x * 256 + threadIdx.x;
    int v = (i < NN) ? g_deg[i] : 0;
    int lane = threadIdx.x & 31, w = threadIdx.x >> 5;
    #pragma unroll
    for (int off = 16; off; off >>= 1)
        v += __shfl_down_sync(0xffffffffu, v, off);
    __shared__ int ws[8];
    if (lane == 0) ws[w] = v;
    __syncthreads();
    if (threadIdx.x == 0) {
        int t = 0;
        #pragma unroll
        for (int q = 0; q < 8; q++) t += ws[q];
        g_part[blockIdx.x] = t;
    }
}

__global__ void scan_apply_kernel() {
    __shared__ int part[256];
    __shared__ int wsum[8];
    int t = threadIdx.x;
    part[t] = (t < NBLK) ? g_part[t] : 0;
    __syncthreads();
    #pragma unroll
    for (int off = 1; off < 256; off <<= 1) {
        int tv = (t >= off) ? part[t - off] : 0;
        __syncthreads();
        part[t] += tv;
        __syncthreads();
    }
    int blockoff = (blockIdx.x > 0) ? part[blockIdx.x - 1] : 0;

    int i = blockIdx.x * 256 + t;
    int d = (i < NN) ? g_deg[i] : 0;
    int lane = t & 31, w = t >> 5;
    int v = d;
    #pragma unroll
    for (int off = 1; off < 32; off <<= 1) {
        int u = __shfl_up_sync(0xffffffffu, v, off);
        if (lane >= off) v += u;
    }
    if (lane == 31) wsum[w] = v;
    __syncthreads();
    if (w == 0) {
        int x = (lane < 8) ? wsum[lane] : 0;
        #pragma unroll
        for (int off = 1; off < 8; off <<= 1) {
            int u = __shfl_up_sync(0xffffffffu, x, off);
            if (lane >= off) x += u;
        }
        if (lane < 8) wsum[lane] = x;
    }
    __syncthreads();
    int excl = (v - d) + (w > 0 ? wsum[w - 1] : 0) + blockoff;
    if (i < NN) {
        g_cursor[i]     = excl;
        g_rowptr[i + 1] = excl + d;
    }
    if (i == 0) g_rowptr[0] = 0;
}

__global__ void scatter_kernel(const int* __restrict__ src, const int* __restrict__ dst) {
    int e = blockIdx.x * blockDim.x + threadIdx.x;
    if (e >= EE) return;
    int s = src[e], d = dst[e];
    int p = atomicAdd(&g_cursor[d], 1);
    g_csrc[p] = s;
    // ew scaled by 2^10 so fp16 stays in normal range (|s-d|<=50000 -> >=0.02)
    g_cew16[p] = __float2half(1024.0f / (float)(s - d));
}

// ------- segment-max via gather: packed half2 math (scaled weights) -------
template <int D>
__global__ void gather_max_kernel(const __half* __restrict__ X, __half* __restrict__ out) {
    const int TPN = D / 16;
    int gid  = blockIdx.x * blockDim.x + threadIdx.x;
    int node = gid / TPN;
    int lane = gid % TPN;
    if (node >= NN) return;
    int s = g_rowptr[node];
    int e = g_rowptr[node + 1];

    const __half NEGH = __ushort_as_half(0xFC00);   // -inf
    __half2 acc[8];
    #pragma unroll
    for (int q = 0; q < 8; q++) acc[q] = __halves2half2(NEGH, NEGH);

    int    sn0 = 0, sn1 = 0;
    __half eh0 = __ushort_as_half(0), eh1 = __ushort_as_half(0);
    if (s + 1 < e) {
        sn0 = g_csrc[s];     sn1 = g_csrc[s + 1];
        eh0 = g_cew16[s];    eh1 = g_cew16[s + 1];
    }

    int j = s;
    for (; j + 1 < e; j += 2) {
        __half2 cw0 = __half2half2(eh0);
        __half2 cw1 = __half2half2(eh1);
        const uint4* r0 = (const uint4*)(X + (size_t)sn0 * D) + lane * 2;
        const uint4* r1 = (const uint4*)(X + (size_t)sn1 * D) + lane * 2;
        uint4 u0a = __ldg(r0);
        uint4 u0b = __ldg(r0 + 1);
        uint4 u1a = __ldg(r1);
        uint4 u1b = __ldg(r1 + 1);
        int nj = j + 2;
        if (nj + 1 < e) {
            sn0 = g_csrc[nj];     sn1 = g_csrc[nj + 1];
            eh0 = g_cew16[nj];    eh1 = g_cew16[nj + 1];
        }
        const uint32_t* p0a = &u0a.x;
        const uint32_t* p0b = &u0b.x;
        const uint32_t* p1a = &u1a.x;
        const uint32_t* p1b = &u1b.x;
        #pragma unroll
        for (int q = 0; q < 4; q++) {
            __half2 a0 = *(const __half2*)&p0a[q];
            __half2 a1 = *(const __half2*)&p1a[q];
            acc[q] = __hmax2(acc[q], __hmax2(__hmul2(a0, cw0), __hmul2(a1, cw1)));
            __half2 b0 = *(const __half2*)&p0b[q];
            __half2 b1 = *(const __half2*)&p1b[q];
            acc[4 + q] = __hmax2(acc[4 + q], __hmax2(__hmul2(b0, cw0), __hmul2(b1, cw1)));
        }
    }
    if (j < e) {   // odd tail (or degree-1 node)
        int    sn = g_csrc[j];
        __half eh = g_cew16[j];
        __half2 cw = __half2half2(eh);
        const uint4* r = (const uint4*)(X + (size_t)sn * D) + lane * 2;
        uint4 ua = __ldg(r);
        uint4 ub = __ldg(r + 1);
        const uint32_t* pa = &ua.x;
        const uint32_t* pb = &ub.x;
        #pragma unroll
        for (int q = 0; q < 4; q++) {
            acc[q]     = __hmax2(acc[q],     __hmul2(*(const __half2*)&pa[q], cw));
            acc[4 + q] = __hmax2(acc[4 + q], __hmul2(*(const __half2*)&pb[q], cw));
        }
    }

    uint4 oa, ob;
    uint32_t* pa = &oa.x;
    uint32_t* pb = &ob.x;
    if (e == s) {
        oa = make_uint4(0, 0, 0, 0);
        ob = make_uint4(0, 0, 0, 0);
    } else {
        const __half2 scl = __float2half2_rn(0.0009765625f);   // exact 2^-10
        #pragma unroll
        for (int q = 0; q < 4; q++) {
            __half2 h0 = __hmul2(acc[q], scl);
            __half2 h1 = __hmul2(acc[4 + q], scl);
            pa[q] = *(uint32_t*)&h0;
            pb[q] = *(uint32_t*)&h1;
        }
    }
    uint4* op = (uint4*)(out + (size_t)node * D) + lane * 2;
    op[0] = oa;
    op[1] = ob;
}

// ---------------- MMA helpers ----------------
__device__ __forceinline__ void mma16816(float* d, const uint32_t* a, const uint32_t* b) {
    asm volatile(
        "mma.sync.aligned.m16n8k16.row.col.f32.f16.f16.f32 "
        "{%0,%1,%2,%3}, {%4,%5,%6,%7}, {%8,%9}, {%0,%1,%2,%3};"
        : "+f"(d[0]), "+f"(d[1]), "+f"(d[2]), "+f"(d[3])
        : "r"(a[0]), "r"(a[1]), "r"(a[2]), "r"(a[3]), "r"(b[0]), "r"(b[1]));
}
__device__ __forceinline__ void ldsm_x4u(uint32_t* r, uint32_t a) {
    asm volatile("ldmatrix.sync.aligned.m8n8.x4.shared.b16 {%0,%1,%2,%3}, [%4];"
                 : "=r"(r[0]), "=r"(r[1]), "=r"(r[2]), "=r"(r[3]) : "r"(a));
}
__device__ __forceinline__ void ldsm_x2u(uint32_t* r, uint32_t a) {
    asm volatile("ldmatrix.sync.aligned.m8n8.x2.shared.b16 {%0,%1}, [%2];"
                 : "=r"(r[0]), "=r"(r[1]) : "r"(a));
}
__device__ __forceinline__ void cp16(uint32_t dst, const void* src, bool v) {
    int sz = v ? 16 : 0;
    asm volatile("cp.async.cg.shared.global [%0], [%1], 16, %2;"
                 :: "r"(dst), "l"(src), "r"(sz));
}

// ------- persistent fp16 mma.sync dual-GEMM: 128x128 tiles, 2 CTA/SM -------
template <typename OutT>
__global__ void __launch_bounds__(256, 2)
mma_dual(const __half* __restrict__ A1, const __half* __restrict__ W1, int K1,
         const __half* __restrict__ A2, const __half* __restrict__ W2, int K2,
         const float* __restrict__ bias, OutT* __restrict__ C, int M, int N)
{
    extern __shared__ __align__(1024) char smem[];
    const uint32_t sbase = (uint32_t)__cvta_generic_to_shared(smem);
    const uint32_t ABYTES = 16384;
    const uint32_t BBYTES = 16384;

    const int tid = threadIdx.x;
    const int wid = tid >> 5, lid = tid & 31;
    const int wm = wid & 1, wn = wid >> 1;
    const int NX = N >> 7;
    const int ntiles = ((M + 127) >> 7) * NX;

    const int nc1 = K1 / 64;
    const int nc2 = A2 ? (K2 / 64) : 0;
    const int nch = nc1 + nc2;

    int t = blockIdx.x;
    if (t >= ntiles) return;
    int row0 = (t / NX) << 7;
    int col0 = (t % NX) << 7;

    auto load_chunk = [&](int c, int buf, int r0, int c0) {
        const int pass = (c >= nc1);
        const __half* A = pass ? A2 : A1;
        const __half* W = pass ? W2 : W1;
        const int K  = pass ? K2 : K1;
        const int k0 = (pass ? (c - nc1) : c) * 64;
        const uint32_t sa  = sbase + (uint32_t)buf * ABYTES;
        const uint32_t sbb = sbase + 2 * ABYTES + (uint32_t)buf * BBYTES;
        int G = tid;
        #pragma unroll
        for (int rep = 0; rep < 4; rep++, G += 256) {
            int row = G >> 3, g = G & 7;
            bool v = (r0 + row) < M;
            size_t r = v ? (size_t)(r0 + row) : 0;
            cp16(sa + SWZ((uint32_t)row * 128 + g * 16), A + r * K + k0 + g * 8, v);
        }
        G = tid;
        #pragma unroll
        for (int rep = 0; rep < 4; rep++, G += 256) {
            int row = G >> 3, g = G & 7;
            cp16(sbb + SWZ((uint32_t)row * 128 + g * 16),
                 W + (size_t)(c0 + row) * K + k0 + g * 8, true);
        }
        asm volatile("cp.async.commit_group;" ::: "memory");
    };

    float acc[4][4][4];
    #pragma unroll
    for (int i = 0; i < 4; i++)
        #pragma unroll
        for (int j = 0; j < 4; j++)
            #pragma unroll
            for (int q = 0; q < 4; q++) acc[i][j][q] = 0.f;

    int buf = 0;
    load_chunk(0, 0, row0, col0);

    while (true) {
        const int nt = t + gridDim.x;
        const bool have_next = nt < ntiles;
        const int nrow0 = have_next ? ((nt / NX) << 7) : 0;
        const int ncol0 = have_next ? ((nt % NX) << 7) : 0;

        for (int c = 0; c < nch; c++) {
            if (c + 1 < nch) {
                load_chunk(c + 1, buf ^ 1, row0, col0);
                asm volatile("cp.async.wait_group 1;" ::: "memory");
            } else if (have_next) {
                load_chunk(0, buf ^ 1, nrow0, ncol0);
                asm volatile("cp.async.wait_group 1;" ::: "memory");
            } else {
                asm volatile("cp.async.wait_group 0;" ::: "memory");
            }
            __syncthreads();

            const uint32_t ca = sbase + (uint32_t)buf * ABYTES;
            const uint32_t cb = sbase + 2 * ABYTES + (uint32_t)buf * BBYTES;
            #pragma unroll
            for (int kb = 0; kb < 4; kb++) {
                uint32_t a[4][4], b[4][2];
                #pragma unroll
                for (int mi = 0; mi < 4; mi++) {
                    uint32_t r = (uint32_t)(wm * 64 + mi * 16 + (lid & 15));
                    ldsm_x4u(a[mi], ca + SWZ(r * 128 + kb * 32 + (lid >> 4) * 16));
                }
                #pragma unroll
                for (int ni = 0; ni < 4; ni++) {
                    uint32_t n = (uint32_t)(wn * 32 + ni * 8 + (lid & 7));
                    ldsm_x2u(b[ni], cb + SWZ(n * 128 + kb * 32 + ((lid >> 3) & 1) * 16));
                }
                #pragma unroll
                for (int mi = 0; mi < 4; mi++)
                    #pragma unroll
                    for (int ni = 0; ni < 4; ni++)
                        mma16816(acc[mi][ni], a[mi], b[ni]);
            }
            __syncthreads();
            buf ^= 1;
        }

        // ---- epilogue (registers + gmem only; overlaps next tile's load) ----
        {
            const int lr = lid >> 2;
            const int lc = (lid & 3) * 2;
            #pragma unroll
            for (int ni = 0; ni < 4; ni++) {
                int col = col0 + wn * 32 + ni * 8 + lc;
                float b0 = bias[col], b1 = bias[col + 1];
                #pragma unroll
                for (int mi = 0; mi < 4; mi++) {
                    int r0 = row0 + wm * 64 + mi * 16 + lr;
                    float* q = acc[mi][ni];
                    if (r0 < M) {
                        float v0 = q[0] + b0, v1 = q[1] + b1;
                        if (sizeof(OutT) == 2) {
                            __half2 h = __floats2half2_rn(v0, v1);
                            *(uint32_t*)((__half*)C + (size_t)r0 * N + col) = *(uint32_t*)&h;
                        } else {
                            *(float2*)((float*)C + (size_t)r0 * N + col) = make_float2(v0, v1);
                        }
                    }
                    if (r0 + 8 < M) {
                        float v0 = q[2] + b0, v1 = q[3] + b1;
                        if (sizeof(OutT) == 2) {
                            __half2 h = __floats2half2_rn(v0, v1);
                            *(uint32_t*)((__half*)C + (size_t)(r0 + 8) * N + col) = *(uint32_t*)&h;
                        } else {
                            *(float2*)((float*)C + (size_t)(r0 + 8) * N + col) = make_float2(v0, v1);
                        }
                    }
                }
            }
        }

        if (!have_next) break;
        t = nt; row0 = nrow0; col0 = ncol0;
        #pragma unroll
        for (int i = 0; i < 4; i++)
            #pragma unroll
            for (int j = 0; j < 4; j++)
                #pragma unroll
                for (int q = 0; q < 4; q++) acc[i][j][q] = 0.f;
    }
}

// ---------------- LayerNorm + ReLU (fp16 in, fp16 out) ----------
__global__ void ln_relu_kernel(const __half* __restrict__ H,
                               const float* __restrict__ gam,
                               const float* __restrict__ bet,
                               __half* __restrict__ out)
{
    int row = blockIdx.x;
    int t   = threadIdx.x;
    uint2 u = *(const uint2*)(H + (size_t)row * DH + t * 4);
    float2 f0 = __half22float2(*(const __half2*)&u.x);
    float2 f1 = __half22float2(*(const __half2*)&u.y);
    float vx = f0.x, vy = f0.y, vz = f1.x, vw = f1.y;
    float s  = vx + vy + vz + vw;
    float ss = vx * vx + vy * vy + vz * vz + vw * vw;
    #pragma unroll
    for (int off = 16; off; off >>= 1) {
        s  += __shfl_down_sync(0xffffffffu, s,  off);
        ss += __shfl_down_sync(0xffffffffu, ss, off);
    }
    __shared__ float sh_s[4], sh_ss[4];
    int w = t >> 5, l = t & 31;
    if (l == 0) { sh_s[w] = s; sh_ss[w] = ss; }
    __syncthreads();
    if (t == 0) {
        float S  = sh_s[0]  + sh_s[1]  + sh_s[2]  + sh_s[3];
        float SS = sh_ss[0] + sh_ss[1] + sh_ss[2] + sh_ss[3];
        float mean = S * (1.0f / DH);
        float var  = SS * (1.0f / DH) - mean * mean;
        sh_s[0]  = mean;
        sh_ss[0] = rsqrtf(var + 1e-5f);
    }
    __syncthreads();
    float mean = sh_s[0], r = sh_ss[0];
    float4 gv = *(const float4*)(gam + t * 4);
    float4 bv = *(const float4*)(bet + t * 4);
    float ox = fmaxf((vx - mean) * r * gv.x + bv.x, 0.f);
    float oy = fmaxf((vy - mean) * r * gv.y + bv.y, 0.f);
    float oz = fmaxf((vz - mean) * r * gv.z + bv.z, 0.f);
    float ow = fmaxf((vw - mean) * r * gv.w + bv.w, 0.f);
    __half2 h0 = __floats2half2_rn(ox, oy);
    __half2 h1 = __floats2half2_rn(oz, ow);
    uint2 o;
    o.x = *(uint32_t*)&h0;
    o.y = *(uint32_t*)&h1;
    *(uint2*)(out + (size_t)row * DH + t * 4) = o;
}

// ---------------- launch --------------------------------------------------
extern "C" void kernel_launch(void* const* d_in, const int* in_sizes, int n_in,
                              void* d_out, int out_size)
{
    const float* x      = (const float*)d_in[0];
    const int*   ei     = (const int*)  d_in[1];
    const float* Wrel1  = (const float*)d_in[3];
    const float* brel1  = (const float*)d_in[4];
    const float* Wroot1 = (const float*)d_in[5];
    const float* g1     = (const float*)d_in[6];
    const float* b1     = (const float*)d_in[7];
    const float* Wrel2  = (const float*)d_in[8];
    const float* brel2  = (const float*)d_in[9];
    const float* Wroot2 = (const float*)d_in[10];
    const float* g2     = (const float*)d_in[11];
    const float* b2     = (const float*)d_in[12];
    const float* Wcls   = (const float*)d_in[13];
    const float* bcls   = (const float*)d_in[14];
    float* out = (float*)d_out;

    const int* src = ei;
    const int* dst = ei + EE;

    __half *pre16, *x16, *agg16, *h16, *w16;
    cudaGetSymbolAddress((void**)&pre16, g_pre16);
    cudaGetSymbolAddress((void**)&x16,   g_x16);
    cudaGetSymbolAddress((void**)&agg16, g_agg16);
    cudaGetSymbolAddress((void**)&h16,   g_h16);
    cudaGetSymbolAddress((void**)&w16,   g_w16);

    __half* wrel1_16  = w16;
    __half* wroot1_16 = w16 + 65536;
    __half* wrel2_16  = w16 + 131072;
    __half* wroot2_16 = w16 + 393216;
    __half* wcls_16   = w16 + 655360;

    const int SMEM_G = 4 * 16384;   // 65536
    cudaFuncSetAttribute((const void*)mma_dual<__half>,
                         cudaFuncAttributeMaxDynamicSharedMemorySize, SMEM_G);
    cudaFuncSetAttribute((const void*)mma_dual<float>,
                         cudaFuncAttributeMaxDynamicSharedMemorySize, SMEM_G);

    f2h_zero_kernel<<<(1780224 + NN + 255) / 256, 256>>>(
        x, Wrel1, Wroot1, Wrel2, Wroot2, Wcls, x16, w16);
    hist_kernel       <<<(EE + 255) / 256, 256>>>(dst);
    deg_partial_kernel<<<NBLK, 256>>>();
    scan_apply_kernel <<<NBLK, 256>>>();
    scatter_kernel    <<<(EE + 255) / 256, 256>>>(src, dst);

    // Layer 1
    gather_max_kernel<DIN><<<(NN * (DIN / 16) + 255) / 256, 256>>>(x16, agg16);
    mma_dual<__half><<<PCTAS, 256, SMEM_G>>>(
        agg16, wrel1_16, DIN, x16, wroot1_16, DIN, brel1, pre16, NN, DH);
    ln_relu_kernel<<<NN, 128>>>(pre16, g1, b1, h16);

    // Layer 2
    gather_max_kernel<DH><<<(NN * (DH / 16) + 255) / 256, 256>>>(h16, agg16);
    mma_dual<__half><<<PCTAS, 256, SMEM_G>>>(
        agg16, wrel2_16, DH, h16, wroot2_16, DH, brel2, pre16, NN, DH);
    ln_relu_kernel<<<NN, 128>>>(pre16, g2, b2, h16);

    // Classifier
    mma_dual<float><<<PCTAS, 256, SMEM_G>>>(
        h16, wcls_16, DH, nullptr, nullptr, 0, bcls, out, NN, NCLS);
}